// round 1
// baseline (speedup 1.0000x reference)
#include <cuda_runtime.h>
#include <cstdint>
#include <cmath>

#define N_KERNELS 2000
#define K_MAX     11
#define SIG_LEN   32768
#define MAX_GROUPS 128
#define THREADS   256
#define UNROLL    4
#define TILE      (THREADS * UNROLL)

// ---------------------------------------------------------------------------
// Parameters passed by value (kernel param space; graph-capture safe, no memcpy)
// ---------------------------------------------------------------------------
struct Params {
    int  idx[N_KERNELS];      // group-ordered -> original kernel index
    int4 gA[MAX_GROUPS];      // {d, p, Lout, G}
    int2 gB[MAX_GROUPS];      // {idx_base, out_off}
};

// ---------------------------------------------------------------------------
// Device kernel: block = (tile of 1024 output positions) x (group) x (sample)
// Every kernel treated as K_MAX=11 taps (weights are zero-padded), so one
// uniform inner loop; out-of-range taps multiply by 0 and/or read 0.
// ---------------------------------------------------------------------------
__global__ void __launch_bounds__(THREADS)
rocket_kernel(const __grid_constant__ Params prm,
              const float* __restrict__ sig,
              const float* __restrict__ W,
              const float* __restrict__ B,
              float* __restrict__ out)
{
    extern __shared__ float smw[];              // [G][12] : 11 weights + bias
    const int g = blockIdx.y;
    const int s = blockIdx.z;
    const int4 ga = prm.gA[g];
    const int d = ga.x, p = ga.y, Lout = ga.z, G = ga.w;
    const int t0 = blockIdx.x * TILE;
    if (t0 >= Lout) return;                     // uniform per block
    const int2 gb = prm.gB[g];

    // Stage this group's weights+biases into shared memory
    for (int j = threadIdx.x; j < G * 12; j += THREADS) {
        int jj = j / 12, q = j - jj * 12;
        int orig = prm.idx[gb.x + jj];
        smw[j] = (q < K_MAX) ? W[orig * K_MAX + q] : B[orig];
    }
    __syncthreads();

    const float* __restrict__ x = sig + s * SIG_LEN;
    const int t = t0 + threadIdx.x;

    // Load the dilated input window once per thread (reused across G kernels)
    float xi[UNROLL][K_MAX];
#pragma unroll
    for (int ii = 0; ii < UNROLL; ii++) {
        const int tt = t + ii * THREADS;
        const int base = tt - p;
#pragma unroll
        for (int q = 0; q < K_MAX; q++) {
            const int pos = base + q * d;
            const bool ok = (tt < Lout) && (pos >= 0) && (pos < SIG_LEN);
            xi[ii][q] = ok ? __ldg(x + pos) : 0.0f;
        }
    }

    for (int j = 0; j < G; j++) {
        float w[K_MAX];
#pragma unroll
        for (int q = 0; q < K_MAX; q++) w[q] = smw[j * 12 + q];
        const float bias = smw[j * 12 + 11];
        const size_t rowbase = (size_t)gb.y + (size_t)(s * G + j) * (size_t)Lout;
#pragma unroll
        for (int ii = 0; ii < UNROLL; ii++) {
            float acc = bias;
#pragma unroll
            for (int q = 0; q < K_MAX; q++) acc = fmaf(w[q], xi[ii][q], acc);
            const int tt = t + ii * THREADS;
            if (tt < Lout) out[rowbase + tt] = acc;
        }
    }
}

// ---------------------------------------------------------------------------
// Host-side bit-exact replication of numpy.random.RandomState(0) meta stream
// ---------------------------------------------------------------------------
namespace mtrep {

struct MT {
    uint32_t mt[624];
    int mti;
    bool has_gauss;
    double gauss_cache;

    void seed(uint32_t s) {
        mt[0] = s;
        for (int i = 1; i < 624; i++)
            mt[i] = 1812433253u * (mt[i - 1] ^ (mt[i - 1] >> 30)) + (uint32_t)i;
        mti = 624;
        has_gauss = false;
        gauss_cache = 0.0;
    }
    uint32_t next() {
        if (mti >= 624) {
            for (int i = 0; i < 624; i++) {
                uint32_t y = (mt[i] & 0x80000000u) | (mt[(i + 1) % 624] & 0x7fffffffu);
                mt[i] = mt[(i + 397) % 624] ^ (y >> 1) ^ ((y & 1u) ? 0x9908b0dfu : 0u);
            }
            mti = 0;
        }
        uint32_t y = mt[mti++];
        y ^= y >> 11;
        y ^= (y << 7) & 0x9d2c5680u;
        y ^= (y << 15) & 0xefc60000u;
        y ^= y >> 18;
        return y;
    }
    // rk_double: 53-bit
    double rd() {
        uint32_t a = next() >> 5, b = next() >> 6;
        return (a * 67108864.0 + b) / 9007199254740992.0;
    }
    // legacy masked-rejection bounded uint (range fits 32 bits)
    uint32_t masked(uint32_t rngmax, uint32_t mask) {
        for (;;) {
            uint32_t v = next() & mask;
            if (v <= rngmax) return v;
        }
    }
    // legacy rk_gauss (polar) with cache
    double gauss() {
        if (has_gauss) { has_gauss = false; return gauss_cache; }
        double x1, x2, r2;
        do {
            x1 = 2.0 * rd() - 1.0;
            x2 = 2.0 * rd() - 1.0;
            r2 = x1 * x1 + x2 * x2;
        } while (r2 >= 1.0 || r2 == 0.0);
        double f = sqrt(-2.0 * log(r2) / r2);
        gauss_cache = f * x1;
        has_gauss = true;
        return f * x2;
    }
};

} // namespace mtrep

extern "C" void kernel_launch(void* const* d_in, const int* in_sizes, int n_in,
                              void* d_out, int out_size)
{
    (void)in_sizes; (void)n_in; (void)out_size;
    const float* sig = (const float*)d_in[0];
    const float* W   = (const float*)d_in[1];
    const float* B   = (const float*)d_in[2];
    float* out       = (float*)d_out;

    // ---- replicate gen_meta() ----
    static int kk[N_KERNELS], dd[N_KERNELS], pp[N_KERNELS];
    {
        mtrep::MT r;
        r.seed(0u);
        for (int i = 0; i < N_KERNELS; i++) {
            uint32_t c = r.masked(2u, 3u);               // choice of 3
            int k = (c == 0u) ? 7 : (c == 1u) ? 9 : 11;
            int emax = (k == 7) ? 12 : 11;               // int(log2((L-1)/(k-1)))
            uint32_t e = r.masked((uint32_t)(emax - 1), 15u);
            int d = 1 << e;
            double rv = r.rd();                          // rng.rand()
            int p = (rv <= 0.5) ? 0 : ((k - 1) * d / 2);
            (void)r.rd();                                // rng.uniform(-1,1) for bias
            for (int q = 0; q < k; q++) (void)r.gauss(); // normal(size=k)
            kk[i] = k; dd[i] = d; pp[i] = p;
        }
    }

    // ---- group by (k,d,p), sort groups lexicographically ----
    static int gk[MAX_GROUPS], gd[MAX_GROUPS], gp[MAX_GROUPS], gcnt[MAX_GROUPS];
    static int gid_of[N_KERNELS];
    int ng = 0;
    for (int i = 0; i < N_KERNELS; i++) {
        int found = -1;
        for (int g = 0; g < ng; g++)
            if (gk[g] == kk[i] && gd[g] == dd[i] && gp[g] == pp[i]) { found = g; break; }
        if (found < 0) {
            found = ng++;
            gk[found] = kk[i]; gd[found] = dd[i]; gp[found] = pp[i]; gcnt[found] = 0;
        }
        gid_of[i] = found;
        gcnt[found]++;
    }
    static int order[MAX_GROUPS];
    for (int g = 0; g < ng; g++) order[g] = g;
    for (int a = 0; a < ng; a++) {                       // selection sort by (k,d,p)
        int best = a;
        for (int b = a + 1; b < ng; b++) {
            int ga_ = order[best], gb_ = order[b];
            bool lt = (gk[gb_] < gk[ga_]) ||
                      (gk[gb_] == gk[ga_] && (gd[gb_] < gd[ga_] ||
                       (gd[gb_] == gd[ga_] && gp[gb_] < gp[ga_])));
            if (lt) best = b;
        }
        int tmp = order[a]; order[a] = order[best]; order[best] = tmp;
    }

    // ---- build params ----
    static Params prm;
    int pos = 0;
    long long off = 0;
    int maxG = 1, maxLout = 1;
    for (int si = 0; si < ng; si++) {
        int g = order[si];
        int G = gcnt[g];
        int Lout = SIG_LEN + 2 * gp[g] - (gk[g] - 1) * gd[g];
        prm.gA[si] = make_int4(gd[g], gp[g], Lout, G);
        prm.gB[si] = make_int2(pos, (int)off);
        for (int i = 0; i < N_KERNELS; i++)
            if (gid_of[i] == g) prm.idx[pos++] = i;
        off += 2LL * G * Lout;
        if (G > maxG) maxG = G;
        if (Lout > maxLout) maxLout = Lout;
    }

    // ---- launch ----
    const int gridx = (maxLout + TILE - 1) / TILE;
    dim3 grid(gridx, ng, 2);
    const int smem = maxG * 12 * (int)sizeof(float);
    rocket_kernel<<<grid, THREADS, smem>>>(prm, sig, W, B, out);
}

// round 2
// speedup vs baseline: 1.1004x; 1.1004x over previous
#include <cuda_runtime.h>
#include <cstdint>
#include <cmath>

#define N_KERNELS 2000
#define K_MAX     11
#define SIG_LEN   32768
#define MAX_GROUPS 128
#define THREADS   256
#define TILE      (THREADS * 4)

// ---------------------------------------------------------------------------
// Parameters passed by value (kernel param space; graph-capture safe)
// ---------------------------------------------------------------------------
struct Params {
    int  idx[N_KERNELS];      // group-ordered -> original kernel index
    int4 gA[MAX_GROUPS];      // {d, p, Lout, G}
    int2 gB[MAX_GROUPS];      // {idx_base, out_off}
};

// ---- packed f32x2 helpers (sm_103a FFMA2 is PTX-only) ----------------------
__device__ __forceinline__ unsigned long long pk(float lo, float hi) {
    unsigned long long r;
    asm("mov.b64 %0, {%1, %2};" : "=l"(r) : "f"(lo), "f"(hi));
    return r;
}
__device__ __forceinline__ unsigned long long fma2(unsigned long long a,
                                                   unsigned long long b,
                                                   unsigned long long c) {
    unsigned long long r;
    asm("fma.rn.f32x2 %0, %1, %2, %3;" : "=l"(r) : "l"(a), "l"(b), "l"(c));
    return r;
}
__device__ __forceinline__ void st2(float* p, unsigned long long v) {
    float lo, hi;
    asm("mov.b64 {%0, %1}, %2;" : "=f"(lo), "=f"(hi) : "l"(v));
    *reinterpret_cast<float2*>(p) = make_float2(lo, hi);
}

// ---------------------------------------------------------------------------
// Device kernel, templated on tap count K. Block = (1024-pos tile, group, sample).
// Each thread owns 4 CONSECUTIVE positions as 2 packed f32x2 accumulators;
// stores are STG.64 (rowbase+t always even since Lout is always even).
// ---------------------------------------------------------------------------
template<int K>
__global__ void __launch_bounds__(THREADS, 3)
rocket_kernel(const __grid_constant__ Params prm, const int gbase,
              const float* __restrict__ sig,
              const float* __restrict__ W,
              const float* __restrict__ B,
              float* __restrict__ out)
{
    extern __shared__ unsigned long long smw[];   // [G][(K+1)] duplicated pairs
    const int g = gbase + blockIdx.y;
    const int s = blockIdx.z;
    const int4 ga = prm.gA[g];
    const int d = ga.x, p = ga.y, Lout = ga.z, G = ga.w;
    const int t0 = blockIdx.x * TILE;
    if (t0 >= Lout) return;
    const int2 gb = prm.gB[g];

    // Stage duplicated weight pairs {w,w} and bias pair {b,b} into smem
    for (int j = threadIdx.x; j < G * (K + 1); j += THREADS) {
        const int jj = j / (K + 1), q = j - jj * (K + 1);
        const int orig = prm.idx[gb.x + jj];
        const float v = (q < K) ? W[orig * K_MAX + q] : B[orig];
        smw[j] = pk(v, v);
    }
    __syncthreads();

    const float* __restrict__ x = sig + s * SIG_LEN;
    const int t = t0 + threadIdx.x * 4;
    const int base = t - p;

    // Dilated input window for 4 consecutive positions, packed as f32x2 pairs.
    unsigned long long xi[K][2];
    if (base >= 0 && base + 3 + (K - 1) * d < SIG_LEN) {
        // interior fast path: no predication
#pragma unroll
        for (int q = 0; q < K; q++) {
            const float* xp = x + base + q * d;
            xi[q][0] = pk(__ldg(xp),     __ldg(xp + 1));
            xi[q][1] = pk(__ldg(xp + 2), __ldg(xp + 3));
        }
    } else {
#pragma unroll
        for (int q = 0; q < K; q++) {
            float v[4];
#pragma unroll
            for (int ii = 0; ii < 4; ii++) {
                const int pos = base + ii + q * d;
                v[ii] = ((unsigned)pos < (unsigned)SIG_LEN) ? __ldg(x + pos) : 0.0f;
            }
            xi[q][0] = pk(v[0], v[1]);
            xi[q][1] = pk(v[2], v[3]);
        }
    }

    float* orow = out + (size_t)gb.y + (size_t)(s * G) * (size_t)Lout + t;
    if (t0 + TILE <= Lout) {
        // full tile: unconditional stores
        for (int j = 0; j < G; j++) {
            const unsigned long long* wr = smw + j * (K + 1);
            unsigned long long a0 = wr[K];   // bias pair
            unsigned long long a1 = a0;
#pragma unroll
            for (int q = 0; q < K; q++) {
                const unsigned long long w = wr[q];
                a0 = fma2(w, xi[q][0], a0);
                a1 = fma2(w, xi[q][1], a1);
            }
            st2(orow, a0);
            st2(orow + 2, a1);
            orow += Lout;
        }
    } else {
        const bool ok0 = (t < Lout);          // Lout even -> pair never straddles
        const bool ok1 = (t + 2 < Lout);
        for (int j = 0; j < G; j++) {
            const unsigned long long* wr = smw + j * (K + 1);
            unsigned long long a0 = wr[K];
            unsigned long long a1 = a0;
#pragma unroll
            for (int q = 0; q < K; q++) {
                const unsigned long long w = wr[q];
                a0 = fma2(w, xi[q][0], a0);
                a1 = fma2(w, xi[q][1], a1);
            }
            if (ok0) st2(orow, a0);
            if (ok1) st2(orow + 2, a1);
            orow += Lout;
        }
    }
}

// ---------------------------------------------------------------------------
// Host-side bit-exact replication of numpy.random.RandomState(0) meta stream
// ---------------------------------------------------------------------------
namespace mtrep {

struct MT {
    uint32_t mt[624];
    int mti;
    bool has_gauss;
    double gauss_cache;

    void seed(uint32_t s) {
        mt[0] = s;
        for (int i = 1; i < 624; i++)
            mt[i] = 1812433253u * (mt[i - 1] ^ (mt[i - 1] >> 30)) + (uint32_t)i;
        mti = 624;
        has_gauss = false;
        gauss_cache = 0.0;
    }
    uint32_t next() {
        if (mti >= 624) {
            for (int i = 0; i < 624; i++) {
                uint32_t y = (mt[i] & 0x80000000u) | (mt[(i + 1) % 624] & 0x7fffffffu);
                mt[i] = mt[(i + 397) % 624] ^ (y >> 1) ^ ((y & 1u) ? 0x9908b0dfu : 0u);
            }
            mti = 0;
        }
        uint32_t y = mt[mti++];
        y ^= y >> 11;
        y ^= (y << 7) & 0x9d2c5680u;
        y ^= (y << 15) & 0xefc60000u;
        y ^= y >> 18;
        return y;
    }
    double rd() {
        uint32_t a = next() >> 5, b = next() >> 6;
        return (a * 67108864.0 + b) / 9007199254740992.0;
    }
    uint32_t masked(uint32_t rngmax, uint32_t mask) {
        for (;;) {
            uint32_t v = next() & mask;
            if (v <= rngmax) return v;
        }
    }
    double gauss() {
        if (has_gauss) { has_gauss = false; return gauss_cache; }
        double x1, x2, r2;
        do {
            x1 = 2.0 * rd() - 1.0;
            x2 = 2.0 * rd() - 1.0;
            r2 = x1 * x1 + x2 * x2;
        } while (r2 >= 1.0 || r2 == 0.0);
        double f = sqrt(-2.0 * log(r2) / r2);
        gauss_cache = f * x1;
        has_gauss = true;
        return f * x2;
    }
};

} // namespace mtrep

extern "C" void kernel_launch(void* const* d_in, const int* in_sizes, int n_in,
                              void* d_out, int out_size)
{
    (void)in_sizes; (void)n_in; (void)out_size;
    const float* sig = (const float*)d_in[0];
    const float* W   = (const float*)d_in[1];
    const float* B   = (const float*)d_in[2];
    float* out       = (float*)d_out;

    // ---- replicate gen_meta() ----
    static int kk[N_KERNELS], dd[N_KERNELS], pp[N_KERNELS];
    {
        mtrep::MT r;
        r.seed(0u);
        for (int i = 0; i < N_KERNELS; i++) {
            uint32_t c = r.masked(2u, 3u);               // choice of 3
            int k = (c == 0u) ? 7 : (c == 1u) ? 9 : 11;
            int emax = (k == 7) ? 12 : 11;               // int(log2((L-1)/(k-1)))
            uint32_t e = r.masked((uint32_t)(emax - 1), 15u);
            int d = 1 << e;
            double rv = r.rd();                          // rng.rand()
            int p = (rv <= 0.5) ? 0 : ((k - 1) * d / 2);
            (void)r.rd();                                // rng.uniform(-1,1) bias
            for (int q = 0; q < k; q++) (void)r.gauss(); // normal(size=k)
            kk[i] = k; dd[i] = d; pp[i] = p;
        }
    }

    // ---- group by (k,d,p), sort groups lexicographically ----
    static int gk[MAX_GROUPS], gd[MAX_GROUPS], gp[MAX_GROUPS], gcnt[MAX_GROUPS];
    static int gid_of[N_KERNELS];
    int ng = 0;
    for (int i = 0; i < N_KERNELS; i++) {
        int found = -1;
        for (int g = 0; g < ng; g++)
            if (gk[g] == kk[i] && gd[g] == dd[i] && gp[g] == pp[i]) { found = g; break; }
        if (found < 0) {
            found = ng++;
            gk[found] = kk[i]; gd[found] = dd[i]; gp[found] = pp[i]; gcnt[found] = 0;
        }
        gid_of[i] = found;
        gcnt[found]++;
    }
    static int order[MAX_GROUPS];
    for (int g = 0; g < ng; g++) order[g] = g;
    for (int a = 0; a < ng; a++) {                       // selection sort by (k,d,p)
        int best = a;
        for (int b = a + 1; b < ng; b++) {
            int ga_ = order[best], gb_ = order[b];
            bool lt = (gk[gb_] < gk[ga_]) ||
                      (gk[gb_] == gk[ga_] && (gd[gb_] < gd[ga_] ||
                       (gd[gb_] == gd[ga_] && gp[gb_] < gp[ga_])));
            if (lt) best = b;
        }
        int tmp = order[a]; order[a] = order[best]; order[best] = tmp;
    }

    // ---- build params + per-k segments ----
    static Params prm;
    int pos = 0;
    long long off = 0;
    // per tap-count class (7/9/11): [start group, end group), maxG, maxLout
    int segs[3] = {0, 0, 0}, sege[3] = {0, 0, 0};
    int segMaxG[3] = {1, 1, 1}, segMaxL[3] = {1, 1, 1};
    for (int si = 0; si < ng; si++) {
        int g = order[si];
        int G = gcnt[g];
        int Lout = SIG_LEN + 2 * gp[g] - (gk[g] - 1) * gd[g];
        prm.gA[si] = make_int4(gd[g], gp[g], Lout, G);
        prm.gB[si] = make_int2(pos, (int)off);
        for (int i = 0; i < N_KERNELS; i++)
            if (gid_of[i] == g) prm.idx[pos++] = i;
        off += 2LL * G * Lout;
        const int c = (gk[g] == 7) ? 0 : (gk[g] == 9) ? 1 : 2;
        if (sege[c] == 0 && segs[c] == 0 && (c == 0 ? si == 0 : sege[c - 1] == si + 0)) {}
        // track segment bounds (groups are contiguous per k because sort key is k-major)
        if (segMaxG[c] == 1 && segMaxL[c] == 1 && sege[c] == 0) segs[c] = si;
        sege[c] = si + 1;
        if (G > segMaxG[c]) segMaxG[c] = G;
        if (Lout > segMaxL[c]) segMaxL[c] = Lout;
    }

    // ---- three templated launches (k = 7, 9, 11) ----
    for (int c = 0; c < 3; c++) {
        const int gcount = sege[c] - segs[c];
        if (gcount <= 0) continue;
        const int K = (c == 0) ? 7 : (c == 1) ? 9 : 11;
        const int gridx = (segMaxL[c] + TILE - 1) / TILE;
        dim3 grid(gridx, gcount, 2);
        const int smem = segMaxG[c] * (K + 1) * (int)sizeof(unsigned long long);
        if (c == 0)
            rocket_kernel<7><<<grid, THREADS, smem>>>(prm, segs[c], sig, W, B, out);
        else if (c == 1)
            rocket_kernel<9><<<grid, THREADS, smem>>>(prm, segs[c], sig, W, B, out);
        else
            rocket_kernel<11><<<grid, THREADS, smem>>>(prm, segs[c], sig, W, B, out);
    }
}